// round 7
// baseline (speedup 1.0000x reference)
#include <cuda_runtime.h>
#include <cstdint>

#define Bb   4
#define Nn   2048
#define DIMc 512
#define Hh   8
#define DHh  64
#define SCALE 0.125f

// Scratch (allocation-free rule: __device__ globals)
__device__ float g_Q[Bb*Nn*DIMc];
__device__ float g_K[Bb*Nn*DIMc];
__device__ float g_V[Bb*Nn*DIMc];
__device__ float g_O[Bb*Nn*DIMc];
__device__ float g_X[Bb*Nn*DIMc];      // pre-rounded input
__device__ float g_Wq[DIMc*DIMc];
__device__ float g_Wk[DIMc*DIMc];
__device__ float g_Wv[DIMc*DIMc];
__device__ float g_Wo[DIMc*DIMc];

__device__ __forceinline__ unsigned f2tf(float x) {
    unsigned u;
    asm("cvt.rna.tf32.f32 %0, %1;" : "=r"(u) : "f"(x));
    return u;
}

__device__ __forceinline__ void mma_tf32(
    float c[4], unsigned a0, unsigned a1, unsigned a2, unsigned a3,
    unsigned b0, unsigned b1)
{
    asm volatile(
        "mma.sync.aligned.m16n8k8.row.col.f32.tf32.tf32.f32 "
        "{%0,%1,%2,%3},{%4,%5,%6,%7},{%8,%9},{%0,%1,%2,%3};\n"
        : "+f"(c[0]), "+f"(c[1]), "+f"(c[2]), "+f"(c[3])
        : "r"(a0), "r"(a1), "r"(a2), "r"(a3), "r"(b0), "r"(b1));
}

__device__ __forceinline__ void cpa16(unsigned saddr, const void* g) {
    asm volatile("cp.async.ca.shared.global [%0], [%1], 16;" :: "r"(saddr), "l"(g));
}
__device__ __forceinline__ void cpa4(unsigned saddr, const void* g) {
    asm volatile("cp.async.ca.shared.global [%0], [%1], 4;" :: "r"(saddr), "l"(g));
}
__device__ __forceinline__ uint32_t smem_u32(const void* p) {
    return (uint32_t)__cvta_generic_to_shared(p);
}

// ---------------------------------------------------------------------------
// Fused pre-pass: tf32-round X and the 4 weight matrices in ONE launch.
// ---------------------------------------------------------------------------
#define NX (Bb*Nn*DIMc)
#define NW (DIMc*DIMc)
#define NTOT (NX + 4*NW)

__global__ __launch_bounds__(256) void round_all_kernel(
    const float* __restrict__ X,  const float* __restrict__ Wq,
    const float* __restrict__ Wk, const float* __restrict__ Wv,
    const float* __restrict__ Wo)
{
    int i = (blockIdx.x * 256 + threadIdx.x) * 4;
    if (i >= NTOT) return;
    const float* s;
    float* d;
    if (i < NX)            { s = X  + i;                 d = g_X  + i; }
    else if (i < NX+NW)    { s = Wq + (i - NX);          d = g_Wq + (i - NX); }
    else if (i < NX+2*NW)  { s = Wk + (i - NX - NW);     d = g_Wk + (i - NX - NW); }
    else if (i < NX+3*NW)  { s = Wv + (i - NX - 2*NW);   d = g_Wv + (i - NX - 2*NW); }
    else                   { s = Wo + (i - NX - 3*NW);   d = g_Wo + (i - NX - 3*NW); }
    float4 v = *(const float4*)s;
    uint4 u;
    u.x = f2tf(v.x); u.y = f2tf(v.y); u.z = f2tf(v.z); u.w = f2tf(v.w);
    *(uint4*)d = u;
}

// ---------------------------------------------------------------------------
// tf32 GEMM v3 (unchanged from R6): block 128x128, 4 warps, warp 64x64,
// BK=32, raw cp.async double-buffered staging, stride 36 (conflict-free).
// ---------------------------------------------------------------------------
#define GSTRIDE 36
#define GBUF (128*GSTRIDE)
#define GEMM_SMEM_BYTES (4*GBUF*4)

template<bool ROUND>
__device__ __forceinline__ void gemm_v3(
    const float* __restrict__ A, const float* __restrict__ W, float* __restrict__ C)
{
    extern __shared__ __align__(16) unsigned gsm[];
    unsigned* As = gsm;
    unsigned* Bs = gsm + 2*GBUF;
    const unsigned sA = smem_u32(As);
    const unsigned sB = smem_u32(Bs);

    const int t    = threadIdx.x;
    const int lane = t & 31;
    const int w    = t >> 5;
    const int q    = lane >> 2;
    const int r    = lane & 3;
    const int wm   = (w >> 1) * 64;
    const int wn   = (w & 1) * 64;
    const int m0   = blockIdx.y * 128;
    const int n0   = blockIdx.x * 128;

    auto stage = [&](int c, int bf) {
        const float* gA = A + m0 * DIMc + c * 32;
        const float* gB = W + n0 * DIMc + c * 32;
        #pragma unroll
        for (int i = 0; i < 8; i++) {
            int id  = t + 128 * i;
            int row = id >> 3, c16 = id & 7;
            unsigned so = (bf*GBUF + row*GSTRIDE + c16*4) * 4;
            cpa16(sA + so, gA + row * DIMc + c16 * 4);
            cpa16(sB + so, gB + row * DIMc + c16 * 4);
        }
        asm volatile("cp.async.commit_group;");
    };

    float acc[4][8][4] = {};
    stage(0, 0);

    #pragma unroll 1
    for (int kt = 0; kt < 16; kt++) {
        const int bf = kt & 1;
        if (kt + 1 < 16) {
            stage(kt + 1, bf ^ 1);
            asm volatile("cp.async.wait_group 1;");
        } else {
            asm volatile("cp.async.wait_group 0;");
        }
        __syncthreads();

        const unsigned* Ab = As + bf*GBUF;
        const unsigned* Bbf = Bs + bf*GBUF;

        #pragma unroll
        for (int s = 0; s < 4; s++) {
            unsigned a[4][4], b[8][2];
            #pragma unroll
            for (int i = 0; i < 4; i++) {
                const int r0 = (wm + 16*i + q) * GSTRIDE + 8*s + r;
                a[i][0] = Ab[r0];
                a[i][1] = Ab[r0 + 8*GSTRIDE];
                a[i][2] = Ab[r0 + 4];
                a[i][3] = Ab[r0 + 8*GSTRIDE + 4];
            }
            #pragma unroll
            for (int j = 0; j < 8; j++) {
                const int bi = (wn + 8*j + q) * GSTRIDE + 8*s + r;
                b[j][0] = Bbf[bi];
                b[j][1] = Bbf[bi + 4];
            }
            #pragma unroll
            for (int i = 0; i < 4; i++)
                #pragma unroll
                for (int j = 0; j < 8; j++)
                    mma_tf32(acc[i][j], a[i][0], a[i][1], a[i][2], a[i][3],
                             b[j][0], b[j][1]);
        }
        __syncthreads();
    }

    #pragma unroll
    for (int i = 0; i < 4; i++) {
        const int row0 = m0 + wm + 16*i + q;
        const int row1 = row0 + 8;
        #pragma unroll
        for (int j = 0; j < 8; j++) {
            const int col = n0 + wn + 8*j + 2*r;
            float2 v0, v1;
            if (ROUND) {
                v0.x = __uint_as_float(f2tf(acc[i][j][0]));
                v0.y = __uint_as_float(f2tf(acc[i][j][1]));
                v1.x = __uint_as_float(f2tf(acc[i][j][2]));
                v1.y = __uint_as_float(f2tf(acc[i][j][3]));
            } else {
                v0.x = acc[i][j][0]; v0.y = acc[i][j][1];
                v1.x = acc[i][j][2]; v1.y = acc[i][j][3];
            }
            *(float2*)&C[row0 * DIMc + col] = v0;
            *(float2*)&C[row1 * DIMc + col] = v1;
        }
    }
}

__global__ __launch_bounds__(128) void qkv_kernel()
{
    const float* W = (blockIdx.z == 0) ? g_Wq : (blockIdx.z == 1) ? g_Wk : g_Wv;
    float* C = (blockIdx.z == 0) ? g_Q : (blockIdx.z == 1) ? g_K : g_V;
    gemm_v3<true>(g_X, W, C);
}

__global__ __launch_bounds__(128) void proj_kernel(float* __restrict__ out)
{
    gemm_v3<false>(g_O, g_Wo, out);
}

// ---------------------------------------------------------------------------
// Attention v6. q-tile 128, 256 threads = 8 warps x 16 q-rows. Register diet
// (~120) + __launch_bounds__(256,2) -> 2 CTAs/SM -> 4 warps/SMSP for latency
// hiding. Same per-row math/key order as v5 -> bitwise-identical results.
// K stride 68 / V natural stride 72 (conflict-free), cp.async double-buffer.
// ---------------------------------------------------------------------------
#define AKW (64*68)
#define AVW (64*72)
#define ATTN_SMEM_BYTES ((2*AKW + 2*AVW + 2*64) * 4)

__global__ __launch_bounds__(256, 2) void attn_kernel(const int* __restrict__ mask)
{
    extern __shared__ __align__(16) unsigned dynsmem[];
    unsigned* KS = dynsmem;                         // [2][AKW]
    unsigned* VS = dynsmem + 2*AKW;                 // [2][AVW]
    int*      MS = (int*)(dynsmem + 2*AKW + 2*AVW); // [2][64]
    const unsigned sK = smem_u32(KS);
    const unsigned sV = smem_u32(VS);
    const unsigned sM = smem_u32(MS);

    const int b    = blockIdx.z;
    const int h    = blockIdx.y;
    const int qt   = blockIdx.x;          // q-tiles of 128
    const int t    = threadIdx.x;
    const int lane = t & 31;
    const int w    = t >> 5;              // 0..7: q rows [16w, 16w+16)
    const int q    = lane >> 2;
    const int r    = lane & 3;

    // Q fragments straight from gmem (pre-rounded tf32 bits)
    unsigned q_a[8][4];
    {
        const float* qb = g_Q + ((size_t)(b*Nn + qt*128 + w*16)) * DIMc + h*DHh;
        #pragma unroll
        for (int s = 0; s < 8; s++) {
            const float* p0 = qb + q * DIMc + 8*s + r;
            q_a[s][0] = __float_as_uint(p0[0]);
            q_a[s][1] = __float_as_uint(p0[8*DIMc]);
            q_a[s][2] = __float_as_uint(p0[4]);
            q_a[s][3] = __float_as_uint(p0[8*DIMc + 4]);
        }
    }

    auto stage = [&](int kt, int bf) {
        #pragma unroll
        for (int i = 0; i < 4; i++) {
            int id  = t + 256 * i;        // 0..1023 chunks
            int row = id >> 4, c4 = id & 15;
            const float* gk = &g_K[(b*Nn + kt*64 + row)*DIMc + h*DHh + c4*4];
            const float* gv = &g_V[(b*Nn + kt*64 + row)*DIMc + h*DHh + c4*4];
            cpa16(sK + (bf*AKW + row*68 + c4*4)*4, gk);
            cpa16(sV + (bf*AVW + row*72 + c4*4)*4, gv);
        }
        if (t < 64) cpa4(sM + (bf*64 + t)*4, &mask[b*Nn + kt*64 + t]);
        asm volatile("cp.async.commit_group;");
    };

    stage(0, 0);

    float o_acc[8][4] = {};
    float lsum0 = 0.f, lsum1 = 0.f;
    const int srcA = 4*q + (r >> 1);
    const int srcB = srcA + 2;
    const bool hi  = (r & 1);

    #pragma unroll 1
    for (int kt = 0; kt < Nn/64; kt++) {
        const int bf = kt & 1;
        if (kt + 1 < Nn/64) {
            stage(kt + 1, bf ^ 1);
            asm volatile("cp.async.wait_group 1;");
        } else {
            asm volatile("cp.async.wait_group 0;");
        }
        __syncthreads();

        const unsigned* Kb = KS + bf*AKW;
        const unsigned* Vb = VS + bf*AVW;
        const int*      mb = MS + bf*64;

        // S = Q @ K^T : 16 q-rows x 64 keys
        float sc[8][4] = {};
        #pragma unroll
        for (int s = 0; s < 8; s++) {
            #pragma unroll
            for (int j = 0; j < 8; j++) {
                const int bi = (8*j + q) * 68 + 8*s + r;
                mma_tf32(sc[j], q_a[s][0], q_a[s][1], q_a[s][2], q_a[s][3],
                         Kb[bi], Kb[bi + 4]);
            }
        }

        // p = exp(S*SCALE); masked -> 1.0 (== exp(1e-9)); row sums
        #pragma unroll
        for (int j = 0; j < 8; j++) {
            const int k0 = 8*j + 2*r;
            const bool m0 = (mb[k0]     != 0);
            const bool m1 = (mb[k0 + 1] != 0);
            float p00 = m0 ? __expf(sc[j][0] * SCALE) : 1.0f;
            float p01 = m1 ? __expf(sc[j][1] * SCALE) : 1.0f;
            float p10 = m0 ? __expf(sc[j][2] * SCALE) : 1.0f;
            float p11 = m1 ? __expf(sc[j][3] * SCALE) : 1.0f;
            lsum0 += p00 + p01;
            lsum1 += p10 + p11;
            sc[j][0] = p00; sc[j][1] = p01; sc[j][2] = p10; sc[j][3] = p11;
        }

        // O += P @ V : shuffle-transpose P into A-fragments
        #pragma unroll
        for (int s2 = 0; s2 < 8; s2++) {
            float x0 = __shfl_sync(0xffffffffu, sc[s2][0], srcA);
            float x1 = __shfl_sync(0xffffffffu, sc[s2][1], srcA);
            float x2 = __shfl_sync(0xffffffffu, sc[s2][2], srcA);
            float x3 = __shfl_sync(0xffffffffu, sc[s2][3], srcA);
            float y0 = __shfl_sync(0xffffffffu, sc[s2][0], srcB);
            float y1 = __shfl_sync(0xffffffffu, sc[s2][1], srcB);
            float y2 = __shfl_sync(0xffffffffu, sc[s2][2], srcB);
            float y3 = __shfl_sync(0xffffffffu, sc[s2][3], srcB);
            const unsigned pa0 = f2tf(hi ? x1 : x0);
            const unsigned pa1 = f2tf(hi ? x3 : x2);
            const unsigned pa2 = f2tf(hi ? y1 : y0);
            const unsigned pa3 = f2tf(hi ? y3 : y2);
            const int krow = (8*s2 + r) * 72;
            #pragma unroll
            for (int j2 = 0; j2 < 8; j2++) {
                const unsigned v0 = Vb[krow + 8*j2 + q];
                const unsigned v1 = Vb[krow + 8*j2 + q + 4*72];
                mma_tf32(o_acc[j2], pa0, pa1, pa2, pa3, v0, v1);
            }
        }
        __syncthreads();  // all warps done with bf before re-staging
    }

    // Normalize and store (tf32-rounded for raw-staged proj GEMM)
    lsum0 += __shfl_xor_sync(0xffffffffu, lsum0, 1);
    lsum0 += __shfl_xor_sync(0xffffffffu, lsum0, 2);
    lsum1 += __shfl_xor_sync(0xffffffffu, lsum1, 1);
    lsum1 += __shfl_xor_sync(0xffffffffu, lsum1, 2);
    const float inv0 = 1.f / lsum0;
    const float inv1 = 1.f / lsum1;
    const int grow = b*Nn + qt*128 + w*16 + q;
    #pragma unroll
    for (int j2 = 0; j2 < 8; j2++) {
        const int col = h*DHh + 8*j2 + 2*r;
        float2 v0, v1;
        v0.x = __uint_as_float(f2tf(o_acc[j2][0] * inv0));
        v0.y = __uint_as_float(f2tf(o_acc[j2][1] * inv0));
        v1.x = __uint_as_float(f2tf(o_acc[j2][2] * inv1));
        v1.y = __uint_as_float(f2tf(o_acc[j2][3] * inv1));
        *(float2*)&g_O[(size_t)grow * DIMc + col]       = v0;
        *(float2*)&g_O[(size_t)(grow + 8) * DIMc + col] = v1;
    }
}

extern "C" void kernel_launch(void* const* d_in, const int* in_sizes, int n_in,
                              void* d_out, int out_size)
{
    const float* X    = (const float*)d_in[0];
    const int*   mask = (const int*)  d_in[1];
    const float* Wq   = (const float*)d_in[2];
    const float* Wk   = (const float*)d_in[3];
    const float* Wv   = (const float*)d_in[4];
    const float* Wout = (const float*)d_in[5];
    float* out = (float*)d_out;

    cudaFuncSetAttribute(attn_kernel,
                         cudaFuncAttributeMaxDynamicSharedMemorySize, ATTN_SMEM_BYTES);
    cudaFuncSetAttribute(qkv_kernel,
                         cudaFuncAttributeMaxDynamicSharedMemorySize, GEMM_SMEM_BYTES);
    cudaFuncSetAttribute(proj_kernel,
                         cudaFuncAttributeMaxDynamicSharedMemorySize, GEMM_SMEM_BYTES);

    round_all_kernel<<<(NTOT/4 + 255)/256, 256>>>(X, Wq, Wk, Wv, Wout);

    dim3 g_qkv(DIMc/128, (Bb*Nn)/128, 3);
    qkv_kernel<<<g_qkv, 128, GEMM_SMEM_BYTES>>>();

    dim3 g_attn(Nn/128, Hh, Bb);
    attn_kernel<<<g_attn, 256, ATTN_SMEM_BYTES>>>(mask);

    dim3 g_proj(DIMc/128, (Bb*Nn)/128, 1);
    proj_kernel<<<g_proj, 128, GEMM_SMEM_BYTES>>>(out);
}

// round 8
// speedup vs baseline: 1.3350x; 1.3350x over previous
#include <cuda_runtime.h>
#include <cstdint>

#define Bb   4
#define Nn   2048
#define DIMc 512
#define Hh   8
#define DHh  64
#define SCALE 0.125f

// Scratch (allocation-free rule: __device__ globals)
__device__ float g_Q[Bb*Nn*DIMc];
__device__ float g_K[Bb*Nn*DIMc];   // rows permuted: unmasked first, masked tail
__device__ float g_V[Bb*Nn*DIMc];   // same permutation
__device__ float g_O[Bb*Nn*DIMc];
__device__ float g_X[Bb*Nn*DIMc];   // pre-rounded input
__device__ float g_Wq[DIMc*DIMc];
__device__ float g_Wk[DIMc*DIMc];
__device__ float g_Wv[DIMc*DIMc];
__device__ float g_Wo[DIMc*DIMc];
__device__ int   g_perm[Bb*Nn];     // within-batch destination row
__device__ int   g_cnt[Bb];         // unmasked count per batch
__device__ float g_C[Bb*DIMc];      // sum of masked V rows per batch

__device__ __forceinline__ unsigned f2tf(float x) {
    unsigned u;
    asm("cvt.rna.tf32.f32 %0, %1;" : "=r"(u) : "f"(x));
    return u;
}

__device__ __forceinline__ void mma_tf32(
    float c[4], unsigned a0, unsigned a1, unsigned a2, unsigned a3,
    unsigned b0, unsigned b1)
{
    asm volatile(
        "mma.sync.aligned.m16n8k8.row.col.f32.tf32.tf32.f32 "
        "{%0,%1,%2,%3},{%4,%5,%6,%7},{%8,%9},{%0,%1,%2,%3};\n"
        : "+f"(c[0]), "+f"(c[1]), "+f"(c[2]), "+f"(c[3])
        : "r"(a0), "r"(a1), "r"(a2), "r"(a3), "r"(b0), "r"(b1));
}

__device__ __forceinline__ void cpa16(unsigned saddr, const void* g) {
    asm volatile("cp.async.ca.shared.global [%0], [%1], 16;" :: "r"(saddr), "l"(g));
}
__device__ __forceinline__ uint32_t smem_u32(const void* p) {
    return (uint32_t)__cvta_generic_to_shared(p);
}

// ---------------------------------------------------------------------------
// Fused pre-pass: tf32-round X and the 4 weight matrices in ONE launch.
// ---------------------------------------------------------------------------
#define NX (Bb*Nn*DIMc)
#define NW (DIMc*DIMc)
#define NTOT (NX + 4*NW)

__global__ __launch_bounds__(256) void round_all_kernel(
    const float* __restrict__ X,  const float* __restrict__ Wq,
    const float* __restrict__ Wk, const float* __restrict__ Wv,
    const float* __restrict__ Wo)
{
    int i = (blockIdx.x * 256 + threadIdx.x) * 4;
    if (i >= NTOT) return;
    const float* s;
    float* d;
    if (i < NX)            { s = X  + i;                 d = g_X  + i; }
    else if (i < NX+NW)    { s = Wq + (i - NX);          d = g_Wq + (i - NX); }
    else if (i < NX+2*NW)  { s = Wk + (i - NX - NW);     d = g_Wk + (i - NX - NW); }
    else if (i < NX+3*NW)  { s = Wv + (i - NX - 2*NW);   d = g_Wv + (i - NX - 2*NW); }
    else                   { s = Wo + (i - NX - 3*NW);   d = g_Wo + (i - NX - 3*NW); }
    float4 v = *(const float4*)s;
    uint4 u;
    u.x = f2tf(v.x); u.y = f2tf(v.y); u.z = f2tf(v.z); u.w = f2tf(v.w);
    *(uint4*)d = u;
}

// ---------------------------------------------------------------------------
// Scan: per batch, stable partition of key indices (unmasked first).
// One CTA per batch, 256 threads, 8 keys each.
// ---------------------------------------------------------------------------
__global__ __launch_bounds__(256) void scan_kernel(const int* __restrict__ mask)
{
    __shared__ int ssum[256];
    __shared__ int cnt_s;
    const int b = blockIdx.x, t = threadIdx.x;
    const int base = b * Nn + t * 8;
    int m[8], s = 0;
    #pragma unroll
    for (int i = 0; i < 8; i++) { m[i] = (mask[base + i] != 0); s += m[i]; }
    ssum[t] = s;
    __syncthreads();
    int ex = 0;
    for (int j = 0; j < t; j++) ex += ssum[j];   // one-time O(256) scan
    if (t == 255) cnt_s = ex + ssum[255];
    __syncthreads();
    const int cnt = cnt_s;
    int u = ex;
    #pragma unroll
    for (int i = 0; i < 8; i++) {
        int n = t * 8 + i;
        g_perm[base + i] = m[i] ? u : cnt + (n - u);
        u += m[i];
    }
    if (t == 0) g_cnt[b] = cnt;
}

// ---------------------------------------------------------------------------
// C_b = sum of masked (tail) V rows. grid (Bb, 4) x 128 threads.
// ---------------------------------------------------------------------------
__global__ __launch_bounds__(128) void cb_kernel()
{
    const int b = blockIdx.x;
    const int c = blockIdx.y * 128 + threadIdx.x;
    const int cnt = g_cnt[b];
    float s = 0.f;
    for (int i = cnt; i < Nn; i++)
        s += g_V[((size_t)b * Nn + i) * DIMc + c];
    g_C[b * DIMc + c] = s;
}

// ---------------------------------------------------------------------------
// tf32 GEMM v3: block 128x128, 4 warps, warp 64x64, BK=32, raw cp.async
// double-buffered, stride 36 (conflict-free). PERM: scatter output rows
// through g_perm (within-batch) for K/V compaction.
// ---------------------------------------------------------------------------
#define GSTRIDE 36
#define GBUF (128*GSTRIDE)
#define GEMM_SMEM_BYTES (4*GBUF*4)

template<bool ROUND, bool PERM>
__device__ __forceinline__ void gemm_v3(
    const float* __restrict__ A, const float* __restrict__ W, float* __restrict__ C)
{
    extern __shared__ __align__(16) unsigned gsm[];
    unsigned* As = gsm;
    unsigned* Bs = gsm + 2*GBUF;
    const unsigned sA = smem_u32(As);
    const unsigned sB = smem_u32(Bs);

    const int t    = threadIdx.x;
    const int lane = t & 31;
    const int w    = t >> 5;
    const int q    = lane >> 2;
    const int r    = lane & 3;
    const int wm   = (w >> 1) * 64;
    const int wn   = (w & 1) * 64;
    const int m0   = blockIdx.y * 128;
    const int n0   = blockIdx.x * 128;

    auto stage = [&](int c, int bf) {
        const float* gA = A + m0 * DIMc + c * 32;
        const float* gB = W + n0 * DIMc + c * 32;
        #pragma unroll
        for (int i = 0; i < 8; i++) {
            int id  = t + 128 * i;
            int row = id >> 3, c16 = id & 7;
            unsigned so = (bf*GBUF + row*GSTRIDE + c16*4) * 4;
            cpa16(sA + so, gA + row * DIMc + c16 * 4);
            cpa16(sB + so, gB + row * DIMc + c16 * 4);
        }
        asm volatile("cp.async.commit_group;");
    };

    float acc[4][8][4] = {};
    stage(0, 0);

    #pragma unroll 1
    for (int kt = 0; kt < 16; kt++) {
        const int bf = kt & 1;
        if (kt + 1 < 16) {
            stage(kt + 1, bf ^ 1);
            asm volatile("cp.async.wait_group 1;");
        } else {
            asm volatile("cp.async.wait_group 0;");
        }
        __syncthreads();

        const unsigned* Ab = As + bf*GBUF;
        const unsigned* Bbf = Bs + bf*GBUF;

        #pragma unroll
        for (int s = 0; s < 4; s++) {
            unsigned a[4][4], b[8][2];
            #pragma unroll
            for (int i = 0; i < 4; i++) {
                const int r0 = (wm + 16*i + q) * GSTRIDE + 8*s + r;
                a[i][0] = Ab[r0];
                a[i][1] = Ab[r0 + 8*GSTRIDE];
                a[i][2] = Ab[r0 + 4];
                a[i][3] = Ab[r0 + 8*GSTRIDE + 4];
            }
            #pragma unroll
            for (int j = 0; j < 8; j++) {
                const int bi = (wn + 8*j + q) * GSTRIDE + 8*s + r;
                b[j][0] = Bbf[bi];
                b[j][1] = Bbf[bi + 4];
            }
            #pragma unroll
            for (int i = 0; i < 4; i++)
                #pragma unroll
                for (int j = 0; j < 8; j++)
                    mma_tf32(acc[i][j], a[i][0], a[i][1], a[i][2], a[i][3],
                             b[j][0], b[j][1]);
        }
        __syncthreads();
    }

    #pragma unroll
    for (int i = 0; i < 4; i++) {
        int row0 = m0 + wm + 16*i + q;
        int row1 = row0 + 8;
        if (PERM) {
            row0 = (row0 & ~(Nn-1)) + g_perm[row0];
            row1 = (row1 & ~(Nn-1)) + g_perm[row1];
        }
        #pragma unroll
        for (int j = 0; j < 8; j++) {
            const int col = n0 + wn + 8*j + 2*r;
            float2 v0, v1;
            if (ROUND) {
                v0.x = __uint_as_float(f2tf(acc[i][j][0]));
                v0.y = __uint_as_float(f2tf(acc[i][j][1]));
                v1.x = __uint_as_float(f2tf(acc[i][j][2]));
                v1.y = __uint_as_float(f2tf(acc[i][j][3]));
            } else {
                v0.x = acc[i][j][0]; v0.y = acc[i][j][1];
                v1.x = acc[i][j][2]; v1.y = acc[i][j][3];
            }
            *(float2*)&C[(size_t)row0 * DIMc + col] = v0;
            *(float2*)&C[(size_t)row1 * DIMc + col] = v1;
        }
    }
}

__global__ __launch_bounds__(128) void qkv_kernel()
{
    if (blockIdx.z == 0)      gemm_v3<true,  false>(g_X, g_Wq, g_Q);
    else if (blockIdx.z == 1) gemm_v3<true,  true >(g_X, g_Wk, g_K);
    else                      gemm_v3<true,  true >(g_X, g_Wv, g_V);
}

__global__ __launch_bounds__(128) void proj_kernel(float* __restrict__ out)
{
    gemm_v3<false, false>(g_O, g_Wo, out);
}

// ---------------------------------------------------------------------------
// Attention v7 (v5 shape + compaction). q-tile 128, 128 threads, 4 warps x
// 32 q-rows (2 m-tiles, B-frags shared). Loops over ceil(cnt/64) compacted
// key tiles; padded tail keys get p=0. Masked contribution added as constant
// C_b / count. K stride 68 / V natural stride 72, cp.async double-buffer.
// ---------------------------------------------------------------------------
#define AKW (64*68)
#define AVW (64*72)
#define ATTN_SMEM_BYTES ((2*AKW + 2*AVW) * 4)

__global__ __launch_bounds__(128) void attn_kernel()
{
    extern __shared__ __align__(16) unsigned dynsmem[];
    unsigned* KS = dynsmem;              // [2][AKW]
    unsigned* VS = dynsmem + 2*AKW;      // [2][AVW]
    const unsigned sK = smem_u32(KS);
    const unsigned sV = smem_u32(VS);

    const int b    = blockIdx.z;
    const int h    = blockIdx.y;
    const int qt   = blockIdx.x;          // q-tiles of 128
    const int t    = threadIdx.x;
    const int lane = t & 31;
    const int w    = t >> 5;              // 0..3: q rows [32w, 32w+32)
    const int q    = lane >> 2;
    const int r    = lane & 3;

    const int n_act  = g_cnt[b];
    const int n_iter = (n_act + 63) >> 6;

    // Q fragments straight from gmem (pre-rounded tf32 bits)
    unsigned q_a[2][8][4];
    {
        const float* qb = g_Q + ((size_t)(b*Nn + qt*128 + w*32)) * DIMc + h*DHh;
        #pragma unroll
        for (int m = 0; m < 2; m++) {
            #pragma unroll
            for (int s = 0; s < 8; s++) {
                const float* p0 = qb + (16*m + q) * DIMc + 8*s + r;
                q_a[m][s][0] = __float_as_uint(p0[0]);
                q_a[m][s][1] = __float_as_uint(p0[8*DIMc]);
                q_a[m][s][2] = __float_as_uint(p0[4]);
                q_a[m][s][3] = __float_as_uint(p0[8*DIMc + 4]);
            }
        }
    }

    auto stage = [&](int kt, int bf) {
        #pragma unroll
        for (int i = 0; i < 8; i++) {
            int id  = t + 128 * i;        // 0..1023 chunks
            int row = id >> 4, c4 = id & 15;
            const float* gk = &g_K[((size_t)b*Nn + kt*64 + row)*DIMc + h*DHh + c4*4];
            const float* gv = &g_V[((size_t)b*Nn + kt*64 + row)*DIMc + h*DHh + c4*4];
            cpa16(sK + (bf*AKW + row*68 + c4*4)*4, gk);
            cpa16(sV + (bf*AVW + row*72 + c4*4)*4, gv);
        }
        asm volatile("cp.async.commit_group;");
    };

    if (n_iter > 0) stage(0, 0);

    float o_acc[2][8][4] = {};
    float lsum[2][2] = {};
    const int srcA = 4*q + (r >> 1);
    const int srcB = srcA + 2;
    const bool hi  = (r & 1);

    #pragma unroll 1
    for (int kt = 0; kt < n_iter; kt++) {
        const int bf = kt & 1;
        if (kt + 1 < n_iter) {
            stage(kt + 1, bf ^ 1);
            asm volatile("cp.async.wait_group 1;");
        } else {
            asm volatile("cp.async.wait_group 0;");
        }
        __syncthreads();

        const unsigned* Kb = KS + bf*AKW;
        const unsigned* Vb = VS + bf*AVW;

        #pragma unroll
        for (int half = 0; half < 2; half++) {
            // S = Q @ K^T : 2 m-tiles x 4 key-groups x 8 k-steps
            float sc[2][4][4] = {};
            #pragma unroll
            for (int s = 0; s < 8; s++) {
                #pragma unroll
                for (int j = 0; j < 4; j++) {
                    const int bi = ((half*4 + j)*8 + q) * 68 + 8*s + r;
                    const unsigned b0 = Kb[bi], b1 = Kb[bi + 4];
                    mma_tf32(sc[0][j], q_a[0][s][0], q_a[0][s][1],
                             q_a[0][s][2], q_a[0][s][3], b0, b1);
                    mma_tf32(sc[1][j], q_a[1][s][0], q_a[1][s][1],
                             q_a[1][s][2], q_a[1][s][3], b0, b1);
                }
            }

            // p = exp(S*SCALE); padded tail keys (>= n_act) -> p = 0
            #pragma unroll
            for (int m = 0; m < 2; m++) {
                #pragma unroll
                for (int j = 0; j < 4; j++) {
                    const int k0 = kt*64 + (half*4 + j)*8 + 2*r;
                    const bool in0 = (k0     < n_act);
                    const bool in1 = (k0 + 1 < n_act);
                    float p00 = in0 ? __expf(sc[m][j][0] * SCALE) : 0.0f;
                    float p01 = in1 ? __expf(sc[m][j][1] * SCALE) : 0.0f;
                    float p10 = in0 ? __expf(sc[m][j][2] * SCALE) : 0.0f;
                    float p11 = in1 ? __expf(sc[m][j][3] * SCALE) : 0.0f;
                    lsum[m][0] += p00 + p01;
                    lsum[m][1] += p10 + p11;
                    sc[m][j][0] = p00; sc[m][j][1] = p01;
                    sc[m][j][2] = p10; sc[m][j][3] = p11;
                }
            }

            // O += P @ V : shuffle-transpose P into A-fragments per m-tile
            #pragma unroll
            for (int s2 = 0; s2 < 4; s2++) {
                unsigned pa[2][4];
                #pragma unroll
                for (int m = 0; m < 2; m++) {
                    float x0 = __shfl_sync(0xffffffffu, sc[m][s2][0], srcA);
                    float x1 = __shfl_sync(0xffffffffu, sc[m][s2][1], srcA);
                    float x2 = __shfl_sync(0xffffffffu, sc[m][s2][2], srcA);
                    float x3 = __shfl_sync(0xffffffffu, sc[m][s2][3], srcA);
                    float y0 = __shfl_sync(0xffffffffu, sc[m][s2][0], srcB);
                    float y1 = __shfl_sync(0xffffffffu, sc[m][s2][1], srcB);
                    float y2 = __shfl_sync(0xffffffffu, sc[m][s2][2], srcB);
                    float y3 = __shfl_sync(0xffffffffu, sc[m][s2][3], srcB);
                    pa[m][0] = f2tf(hi ? x1 : x0);
                    pa[m][1] = f2tf(hi ? x3 : x2);
                    pa[m][2] = f2tf(hi ? y1 : y0);
                    pa[m][3] = f2tf(hi ? y3 : y2);
                }
                const int krow = (half*32 + 8*s2 + r) * 72;
                #pragma unroll
                for (int j2 = 0; j2 < 8; j2++) {
                    const unsigned v0 = Vb[krow + 8*j2 + q];
                    const unsigned v1 = Vb[krow + 8*j2 + q + 4*72];
                    mma_tf32(o_acc[0][j2], pa[0][0], pa[0][1], pa[0][2], pa[0][3], v0, v1);
                    mma_tf32(o_acc[1][j2], pa[1][0], pa[1][1], pa[1][2], pa[1][3], v0, v1);
                }
            }
        }
        __syncthreads();  // all warps done with bf before re-staging
    }

    // Masked keys contribute p=1: +count to denominator, +C_b to numerator.
    const float mcount = (float)(Nn - n_act);
    #pragma unroll
    for (int m = 0; m < 2; m++) {
        float l0 = lsum[m][0], l1 = lsum[m][1];
        l0 += __shfl_xor_sync(0xffffffffu, l0, 1);
        l0 += __shfl_xor_sync(0xffffffffu, l0, 2);
        l1 += __shfl_xor_sync(0xffffffffu, l1, 1);
        l1 += __shfl_xor_sync(0xffffffffu, l1, 2);
        const float inv0 = 1.f / (l0 + mcount);
        const float inv1 = 1.f / (l1 + mcount);
        const int grow = b*Nn + qt*128 + w*32 + 16*m + q;
        #pragma unroll
        for (int j2 = 0; j2 < 8; j2++) {
            const int col = h*DHh + 8*j2 + 2*r;
            const float2 cv = *(const float2*)&g_C[b*DIMc + col];
            float2 v0, v1;
            v0.x = __uint_as_float(f2tf((o_acc[m][j2][0] + cv.x) * inv0));
            v0.y = __uint_as_float(f2tf((o_acc[m][j2][1] + cv.y) * inv0));
            v1.x = __uint_as_float(f2tf((o_acc[m][j2][2] + cv.x) * inv1));
            v1.y = __uint_as_float(f2tf((o_acc[m][j2][3] + cv.y) * inv1));
            *(float2*)&g_O[(size_t)grow * DIMc + col]       = v0;
            *(float2*)&g_O[(size_t)(grow + 8) * DIMc + col] = v1;
        }
    }
}

extern "C" void kernel_launch(void* const* d_in, const int* in_sizes, int n_in,
                              void* d_out, int out_size)
{
    const float* X    = (const float*)d_in[0];
    const int*   mask = (const int*)  d_in[1];
    const float* Wq   = (const float*)d_in[2];
    const float* Wk   = (const float*)d_in[3];
    const float* Wv   = (const float*)d_in[4];
    const float* Wout = (const float*)d_in[5];
    float* out = (float*)d_out;

    cudaFuncSetAttribute(attn_kernel,
                         cudaFuncAttributeMaxDynamicSharedMemorySize, ATTN_SMEM_BYTES);
    cudaFuncSetAttribute(qkv_kernel,
                         cudaFuncAttributeMaxDynamicSharedMemorySize, GEMM_SMEM_BYTES);
    cudaFuncSetAttribute(proj_kernel,
                         cudaFuncAttributeMaxDynamicSharedMemorySize, GEMM_SMEM_BYTES);

    round_all_kernel<<<(NTOT/4 + 255)/256, 256>>>(X, Wq, Wk, Wv, Wout);
    scan_kernel<<<Bb, 256>>>(mask);

    dim3 g_qkv(DIMc/128, (Bb*Nn)/128, 3);
    qkv_kernel<<<g_qkv, 128, GEMM_SMEM_BYTES>>>();

    cb_kernel<<<dim3(Bb, 4), 128>>>();

    dim3 g_attn(Nn/128, Hh, Bb);
    attn_kernel<<<g_attn, 128, ATTN_SMEM_BYTES>>>();

    dim3 g_proj(DIMc/128, (Bb*Nn)/128, 1);
    proj_kernel<<<g_proj, 128, GEMM_SMEM_BYTES>>>(out);
}

// round 11
// speedup vs baseline: 1.4561x; 1.0908x over previous
#include <cuda_runtime.h>
#include <cstdint>

#define Bb   4
#define Nn   2048
#define DIMc 512
#define Hh   8
#define DHh  64
#define SCALE 0.125f

// Scratch (allocation-free rule: __device__ globals)
__device__ float g_Q[Bb*Nn*DIMc];
__device__ float g_K[Bb*Nn*DIMc];   // rows permuted: unmasked first, masked tail
__device__ float g_V[Bb*Nn*DIMc];   // same permutation
__device__ float g_O[Bb*Nn*DIMc];
__device__ float g_X[Bb*Nn*DIMc];   // pre-rounded input
__device__ float g_Wq[DIMc*DIMc];
__device__ float g_Wk[DIMc*DIMc];
__device__ float g_Wv[DIMc*DIMc];
__device__ float g_Wo[DIMc*DIMc];
__device__ int   g_perm[Bb*Nn];     // within-batch destination row
__device__ int   g_cnt[Bb];         // unmasked count per batch
__device__ float g_C[Bb*DIMc];      // sum of masked V rows per batch

__device__ __forceinline__ unsigned f2tf(float x) {
    unsigned u;
    asm("cvt.rna.tf32.f32 %0, %1;" : "=r"(u) : "f"(x));
    return u;
}

__device__ __forceinline__ void mma_tf32(
    float c[4], unsigned a0, unsigned a1, unsigned a2, unsigned a3,
    unsigned b0, unsigned b1)
{
    asm volatile(
        "mma.sync.aligned.m16n8k8.row.col.f32.tf32.tf32.f32 "
        "{%0,%1,%2,%3},{%4,%5,%6,%7},{%8,%9},{%0,%1,%2,%3};\n"
        : "+f"(c[0]), "+f"(c[1]), "+f"(c[2]), "+f"(c[3])
        : "r"(a0), "r"(a1), "r"(a2), "r"(a3), "r"(b0), "r"(b1));
}

__device__ __forceinline__ void cpa16(unsigned saddr, const void* g) {
    asm volatile("cp.async.ca.shared.global [%0], [%1], 16;" :: "r"(saddr), "l"(g));
}
__device__ __forceinline__ uint32_t smem_u32(const void* p) {
    return (uint32_t)__cvta_generic_to_shared(p);
}

// ---------------------------------------------------------------------------
// Fused pre-pass: tf32-round X and the 4 weight matrices in ONE launch.
// ---------------------------------------------------------------------------
#define NX (Bb*Nn*DIMc)
#define NW (DIMc*DIMc)
#define NTOT (NX + 4*NW)

__global__ __launch_bounds__(256) void round_all_kernel(
    const float* __restrict__ X,  const float* __restrict__ Wq,
    const float* __restrict__ Wk, const float* __restrict__ Wv,
    const float* __restrict__ Wo)
{
    int i = (blockIdx.x * 256 + threadIdx.x) * 4;
    if (i >= NTOT) return;
    const float* s;
    float* d;
    if (i < NX)            { s = X  + i;                 d = g_X  + i; }
    else if (i < NX+NW)    { s = Wq + (i - NX);          d = g_Wq + (i - NX); }
    else if (i < NX+2*NW)  { s = Wk + (i - NX - NW);     d = g_Wk + (i - NX - NW); }
    else if (i < NX+3*NW)  { s = Wv + (i - NX - 2*NW);   d = g_Wv + (i - NX - 2*NW); }
    else                   { s = Wo + (i - NX - 3*NW);   d = g_Wo + (i - NX - 3*NW); }
    float4 v = *(const float4*)s;
    uint4 u;
    u.x = f2tf(v.x); u.y = f2tf(v.y); u.z = f2tf(v.z); u.w = f2tf(v.w);
    *(uint4*)d = u;
}

// ---------------------------------------------------------------------------
// Scan: per batch, stable partition of key indices (unmasked first).
// One CTA per batch, 256 threads, 8 keys each.
// ---------------------------------------------------------------------------
__global__ __launch_bounds__(256) void scan_kernel(const int* __restrict__ mask)
{
    __shared__ int ssum[256];
    __shared__ int cnt_s;
    const int b = blockIdx.x, t = threadIdx.x;
    const int base = b * Nn + t * 8;
    int m[8], s = 0;
    #pragma unroll
    for (int i = 0; i < 8; i++) { m[i] = (mask[base + i] != 0); s += m[i]; }
    ssum[t] = s;
    __syncthreads();
    int ex = 0;
    for (int j = 0; j < t; j++) ex += ssum[j];   // one-time O(256) scan
    if (t == 255) cnt_s = ex + ssum[255];
    __syncthreads();
    const int cnt = cnt_s;
    int u = ex;
    #pragma unroll
    for (int i = 0; i < 8; i++) {
        int n = t * 8 + i;
        g_perm[base + i] = m[i] ? u : cnt + (n - u);
        u += m[i];
    }
    if (t == 0) g_cnt[b] = cnt;
}

// ---------------------------------------------------------------------------
// Zero g_C (Bb*DIMc floats) before cb accumulation.
// ---------------------------------------------------------------------------
__global__ __launch_bounds__(256) void zero_c_kernel()
{
    int i = blockIdx.x * 256 + threadIdx.x;
    if (i < Bb * DIMc) g_C[i] = 0.f;
}

// ---------------------------------------------------------------------------
// C_b = sum of masked (tail) V rows. Parallel: grid (Bb, 16) x 128 threads.
// Each block sums a chunk of tail rows with fully coalesced float4 reads,
// then atomicAdd into g_C.
// ---------------------------------------------------------------------------
__global__ __launch_bounds__(128) void cb_kernel()
{
    const int b = blockIdx.x;
    const int j = blockIdx.y;                // chunk 0..15
    const int t = threadIdx.x;               // 128 threads x float4 = 512 cols
    const int cnt   = g_cnt[b];
    const int nmask = Nn - cnt;
    const int chunk = (nmask + 15) >> 4;
    const int start = cnt + j * chunk;
    int end = start + chunk;
    if (end > Nn) end = Nn;
    if (start >= end) return;

    float4 s = make_float4(0.f, 0.f, 0.f, 0.f);
    const float* vb = g_V + (size_t)b * Nn * DIMc + t * 4;
    for (int i = start; i < end; i++) {
        float4 v = *(const float4*)(vb + (size_t)i * DIMc);
        s.x += v.x; s.y += v.y; s.z += v.z; s.w += v.w;
    }
    float* c = g_C + b * DIMc + t * 4;
    atomicAdd(c + 0, s.x);
    atomicAdd(c + 1, s.y);
    atomicAdd(c + 2, s.z);
    atomicAdd(c + 3, s.w);
}

// ---------------------------------------------------------------------------
// tf32 GEMM v3: block 128x128, 4 warps, warp 64x64, BK=32, raw cp.async
// double-buffered, stride 36 (conflict-free). PERM: scatter output rows
// through g_perm (within-batch) for K/V compaction.
// ---------------------------------------------------------------------------
#define GSTRIDE 36
#define GBUF (128*GSTRIDE)
#define GEMM_SMEM_BYTES (4*GBUF*4)

template<bool ROUND, bool PERM>
__device__ __forceinline__ void gemm_v3(
    const float* __restrict__ A, const float* __restrict__ W, float* __restrict__ C)
{
    extern __shared__ __align__(16) unsigned gsm[];
    unsigned* As = gsm;
    unsigned* Bs = gsm + 2*GBUF;
    const unsigned sA = smem_u32(As);
    const unsigned sB = smem_u32(Bs);

    const int t    = threadIdx.x;
    const int lane = t & 31;
    const int w    = t >> 5;
    const int q    = lane >> 2;
    const int r    = lane & 3;
    const int wm   = (w >> 1) * 64;
    const int wn   = (w & 1) * 64;
    const int m0   = blockIdx.y * 128;
    const int n0   = blockIdx.x * 128;

    auto stage = [&](int c, int bf) {
        const float* gA = A + m0 * DIMc + c * 32;
        const float* gB = W + n0 * DIMc + c * 32;
        #pragma unroll
        for (int i = 0; i < 8; i++) {
            int id  = t + 128 * i;
            int row = id >> 3, c16 = id & 7;
            unsigned so = (bf*GBUF + row*GSTRIDE + c16*4) * 4;
            cpa16(sA + so, gA + row * DIMc + c16 * 4);
            cpa16(sB + so, gB + row * DIMc + c16 * 4);
        }
        asm volatile("cp.async.commit_group;");
    };

    float acc[4][8][4] = {};
    stage(0, 0);

    #pragma unroll 1
    for (int kt = 0; kt < 16; kt++) {
        const int bf = kt & 1;
        if (kt + 1 < 16) {
            stage(kt + 1, bf ^ 1);
            asm volatile("cp.async.wait_group 1;");
        } else {
            asm volatile("cp.async.wait_group 0;");
        }
        __syncthreads();

        const unsigned* Ab = As + bf*GBUF;
        const unsigned* Bbf = Bs + bf*GBUF;

        #pragma unroll
        for (int s = 0; s < 4; s++) {
            unsigned a[4][4], b[8][2];
            #pragma unroll
            for (int i = 0; i < 4; i++) {
                const int r0 = (wm + 16*i + q) * GSTRIDE + 8*s + r;
                a[i][0] = Ab[r0];
                a[i][1] = Ab[r0 + 8*GSTRIDE];
                a[i][2] = Ab[r0 + 4];
                a[i][3] = Ab[r0 + 8*GSTRIDE + 4];
            }
            #pragma unroll
            for (int j = 0; j < 8; j++) {
                const int bi = (wn + 8*j + q) * GSTRIDE + 8*s + r;
                b[j][0] = Bbf[bi];
                b[j][1] = Bbf[bi + 4];
            }
            #pragma unroll
            for (int i = 0; i < 4; i++)
                #pragma unroll
                for (int j = 0; j < 8; j++)
                    mma_tf32(acc[i][j], a[i][0], a[i][1], a[i][2], a[i][3],
                             b[j][0], b[j][1]);
        }
        __syncthreads();
    }

    #pragma unroll
    for (int i = 0; i < 4; i++) {
        int row0 = m0 + wm + 16*i + q;
        int row1 = row0 + 8;
        if (PERM) {
            row0 = (row0 & ~(Nn-1)) + g_perm[row0];
            row1 = (row1 & ~(Nn-1)) + g_perm[row1];
        }
        #pragma unroll
        for (int j = 0; j < 8; j++) {
            const int col = n0 + wn + 8*j + 2*r;
            float2 v0, v1;
            if (ROUND) {
                v0.x = __uint_as_float(f2tf(acc[i][j][0]));
                v0.y = __uint_as_float(f2tf(acc[i][j][1]));
                v1.x = __uint_as_float(f2tf(acc[i][j][2]));
                v1.y = __uint_as_float(f2tf(acc[i][j][3]));
            } else {
                v0.x = acc[i][j][0]; v0.y = acc[i][j][1];
                v1.x = acc[i][j][2]; v1.y = acc[i][j][3];
            }
            *(float2*)&C[(size_t)row0 * DIMc + col] = v0;
            *(float2*)&C[(size_t)row1 * DIMc + col] = v1;
        }
    }
}

__global__ __launch_bounds__(128) void qkv_kernel()
{
    if (blockIdx.z == 0)      gemm_v3<true,  false>(g_X, g_Wq, g_Q);
    else if (blockIdx.z == 1) gemm_v3<true,  true >(g_X, g_Wk, g_K);
    else                      gemm_v3<true,  true >(g_X, g_Wv, g_V);
}

__global__ __launch_bounds__(128) void proj_kernel(float* __restrict__ out)
{
    gemm_v3<false, false>(g_O, g_Wo, out);
}

// ---------------------------------------------------------------------------
// Attention v7 (compacted keys). q-tile 128, 128 threads, 4 warps x 32 q-rows
// (2 m-tiles, B-frags shared). Loops over ceil(cnt/64) compacted key tiles;
// padded tail keys get p=0. Masked contribution added as constant C_b/count.
// K stride 68 / V natural stride 72, cp.async double-buffer.
// ---------------------------------------------------------------------------
#define AKW (64*68)
#define AVW (64*72)
#define ATTN_SMEM_BYTES ((2*AKW + 2*AVW) * 4)

__global__ __launch_bounds__(128) void attn_kernel()
{
    extern __shared__ __align__(16) unsigned dynsmem[];
    unsigned* KS = dynsmem;              // [2][AKW]
    unsigned* VS = dynsmem + 2*AKW;      // [2][AVW]
    const unsigned sK = smem_u32(KS);
    const unsigned sV = smem_u32(VS);

    const int b    = blockIdx.z;
    const int h    = blockIdx.y;
    const int qt   = blockIdx.x;          // q-tiles of 128
    const int t    = threadIdx.x;
    const int lane = t & 31;
    const int w    = t >> 5;              // 0..3: q rows [32w, 32w+32)
    const int q    = lane >> 2;
    const int r    = lane & 3;

    const int n_act  = g_cnt[b];
    const int n_iter = (n_act + 63) >> 6;

    // Q fragments straight from gmem (pre-rounded tf32 bits)
    unsigned q_a[2][8][4];
    {
        const float* qb = g_Q + ((size_t)(b*Nn + qt*128 + w*32)) * DIMc + h*DHh;
        #pragma unroll
        for (int m = 0; m < 2; m++) {
            #pragma unroll
            for (int s = 0; s < 8; s++) {
                const float* p0 = qb + (16*m + q) * DIMc + 8*s + r;
                q_a[m][s][0] = __float_as_uint(p0[0]);
                q_a[m][s][1] = __float_as_uint(p0[8*DIMc]);
                q_a[m][s][2] = __float_as_uint(p0[4]);
                q_a[m][s][3] = __float_as_uint(p0[8*DIMc + 4]);
            }
        }
    }

    auto stage = [&](int kt, int bf) {
        #pragma unroll
        for (int i = 0; i < 8; i++) {
            int id  = t + 128 * i;        // 0..1023 chunks
            int row = id >> 4, c4 = id & 15;
            const float* gk = &g_K[((size_t)b*Nn + kt*64 + row)*DIMc + h*DHh + c4*4];
            const float* gv = &g_V[((size_t)b*Nn + kt*64 + row)*DIMc + h*DHh + c4*4];
            cpa16(sK + (bf*AKW + row*68 + c4*4)*4, gk);
            cpa16(sV + (bf*AVW + row*72 + c4*4)*4, gv);
        }
        asm volatile("cp.async.commit_group;");
    };

    if (n_iter > 0) stage(0, 0);

    float o_acc[2][8][4] = {};
    float lsum[2][2] = {};
    const int srcA = 4*q + (r >> 1);
    const int srcB = srcA + 2;
    const bool hi  = (r & 1);

    #pragma unroll 1
    for (int kt = 0; kt < n_iter; kt++) {
        const int bf = kt & 1;
        if (kt + 1 < n_iter) {
            stage(kt + 1, bf ^ 1);
            asm volatile("cp.async.wait_group 1;");
        } else {
            asm volatile("cp.async.wait_group 0;");
        }
        __syncthreads();

        const unsigned* Kb = KS + bf*AKW;
        const unsigned* Vb = VS + bf*AVW;

        #pragma unroll
        for (int half = 0; half < 2; half++) {
            // S = Q @ K^T : 2 m-tiles x 4 key-groups x 8 k-steps
            float sc[2][4][4] = {};
            #pragma unroll
            for (int s = 0; s < 8; s++) {
                #pragma unroll
                for (int j = 0; j < 4; j++) {
                    const int bi = ((half*4 + j)*8 + q) * 68 + 8*s + r;
                    const unsigned b0 = Kb[bi], b1 = Kb[bi + 4];
                    mma_tf32(sc[0][j], q_a[0][s][0], q_a[0][s][1],
                             q_a[0][s][2], q_a[0][s][3], b0, b1);
                    mma_tf32(sc[1][j], q_a[1][s][0], q_a[1][s][1],
                             q_a[1][s][2], q_a[1][s][3], b0, b1);
                }
            }

            // p = exp(S*SCALE); padded tail keys (>= n_act) -> p = 0
            #pragma unroll
            for (int m = 0; m < 2; m++) {
                #pragma unroll
                for (int j = 0; j < 4; j++) {
                    const int k0 = kt*64 + (half*4 + j)*8 + 2*r;
                    const bool in0 = (k0     < n_act);
                    const bool in1 = (k0 + 1 < n_act);
                    float p00 = in0 ? __expf(sc[m][j][0] * SCALE) : 0.0f;
                    float p01 = in1 ? __expf(sc[m][j][1] * SCALE) : 0.0f;
                    float p10 = in0 ? __expf(sc[m][j][2] * SCALE) : 0.0f;
                    float p11 = in1 ? __expf(sc[m][j][3] * SCALE) : 0.0f;
                    lsum[m][0] += p00 + p01;
                    lsum[m][1] += p10 + p11;
                    sc[m][j][0] = p00; sc[m][j][1] = p01;
                    sc[m][j][2] = p10; sc[m][j][3] = p11;
                }
            }

            // O += P @ V : shuffle-transpose P into A-fragments per m-tile
            #pragma unroll
            for (int s2 = 0; s2 < 4; s2++) {
                unsigned pa[2][4];
                #pragma unroll
                for (int m = 0; m < 2; m++) {
                    float x0 = __shfl_sync(0xffffffffu, sc[m][s2][0], srcA);
                    float x1 = __shfl_sync(0xffffffffu, sc[m][s2][1], srcA);
                    float x2 = __shfl_sync(0xffffffffu, sc[m][s2][2], srcA);
                    float x3 = __shfl_sync(0xffffffffu, sc[m][s2][3], srcA);
                    float y0 = __shfl_sync(0xffffffffu, sc[m][s2][0], srcB);
                    float y1 = __shfl_sync(0xffffffffu, sc[m][s2][1], srcB);
                    float y2 = __shfl_sync(0xffffffffu, sc[m][s2][2], srcB);
                    float y3 = __shfl_sync(0xffffffffu, sc[m][s2][3], srcB);
                    pa[m][0] = f2tf(hi ? x1 : x0);
                    pa[m][1] = f2tf(hi ? x3 : x2);
                    pa[m][2] = f2tf(hi ? y1 : y0);
                    pa[m][3] = f2tf(hi ? y3 : y2);
                }
                const int krow = (half*32 + 8*s2 + r) * 72;
                #pragma unroll
                for (int j2 = 0; j2 < 8; j2++) {
                    const unsigned v0 = Vb[krow + 8*j2 + q];
                    const unsigned v1 = Vb[krow + 8*j2 + q + 4*72];
                    mma_tf32(o_acc[0][j2], pa[0][0], pa[0][1], pa[0][2], pa[0][3], v0, v1);
                    mma_tf32(o_acc[1][j2], pa[1][0], pa[1][1], pa[1][2], pa[1][3], v0, v1);
                }
            }
        }
        __syncthreads();  // all warps done with bf before re-staging
    }

    // Masked keys contribute p=1: +count to denominator, +C_b to numerator.
    const float mcount = (float)(Nn - n_act);
    #pragma unroll
    for (int m = 0; m < 2; m++) {
        float l0 = lsum[m][0], l1 = lsum[m][1];
        l0 += __shfl_xor_sync(0xffffffffu, l0, 1);
        l0 += __shfl_xor_sync(0xffffffffu, l0, 2);
        l1 += __shfl_xor_sync(0xffffffffu, l1, 1);
        l1 += __shfl_xor_sync(0xffffffffu, l1, 2);
        const float inv0 = 1.f / (l0 + mcount);
        const float inv1 = 1.f / (l1 + mcount);
        const int grow = b*Nn + qt*128 + w*32 + 16*m + q;
        #pragma unroll
        for (int j2 = 0; j2 < 8; j2++) {
            const int col = h*DHh + 8*j2 + 2*r;
            const float2 cv = *(const float2*)&g_C[b*DIMc + col];
            float2 v0, v1;
            v0.x = __uint_as_float(f2tf((o_acc[m][j2][0] + cv.x) * inv0));
            v0.y = __uint_as_float(f2tf((o_acc[m][j2][1] + cv.y) * inv0));
            v1.x = __uint_as_float(f2tf((o_acc[m][j2][2] + cv.x) * inv1));
            v1.y = __uint_as_float(f2tf((o_acc[m][j2][3] + cv.y) * inv1));
            *(float2*)&g_O[(size_t)grow * DIMc + col]       = v0;
            *(float2*)&g_O[(size_t)(grow + 8) * DIMc + col] = v1;
        }
    }
}

extern "C" void kernel_launch(void* const* d_in, const int* in_sizes, int n_in,
                              void* d_out, int out_size)
{
    const float* X    = (const float*)d_in[0];
    const int*   mask = (const int*)  d_in[1];
    const float* Wq   = (const float*)d_in[2];
    const float* Wk   = (const float*)d_in[3];
    const float* Wv   = (const float*)d_in[4];
    const float* Wout = (const float*)d_in[5];
    float* out = (float*)d_out;

    cudaFuncSetAttribute(attn_kernel,
                         cudaFuncAttributeMaxDynamicSharedMemorySize, ATTN_SMEM_BYTES);
    cudaFuncSetAttribute(qkv_kernel,
                         cudaFuncAttributeMaxDynamicSharedMemorySize, GEMM_SMEM_BYTES);
    cudaFuncSetAttribute(proj_kernel,
                         cudaFuncAttributeMaxDynamicSharedMemorySize, GEMM_SMEM_BYTES);

    round_all_kernel<<<(NTOT/4 + 255)/256, 256>>>(X, Wq, Wk, Wv, Wout);
    scan_kernel<<<Bb, 256>>>(mask);
    zero_c_kernel<<<(Bb*DIMc + 255)/256, 256>>>();

    dim3 g_qkv(DIMc/128, (Bb*Nn)/128, 3);
    qkv_kernel<<<g_qkv, 128, GEMM_SMEM_BYTES>>>();

    cb_kernel<<<dim3(Bb, 16), 128>>>();

    dim3 g_attn(Nn/128, Hh, Bb);
    attn_kernel<<<g_attn, 128, ATTN_SMEM_BYTES>>>();

    dim3 g_proj(DIMc/128, (Bb*Nn)/128, 1);
    proj_kernel<<<g_proj, 128, GEMM_SMEM_BYTES>>>(out);
}

// round 15
// speedup vs baseline: 1.4825x; 1.0181x over previous
#include <cuda_runtime.h>
#include <cstdint>

#define Bb   4
#define Nn   2048
#define DIMc 512
#define Hh   8
#define DHh  64
#define SCALE 0.125f

// Scratch (allocation-free rule: __device__ globals)
__device__ float g_Q[Bb*Nn*DIMc];   // row-major
__device__ float g_K[Bb*Nn*DIMc];   // row-major, rows permuted (unmasked first)
__device__ float g_V[Bb*Nn*DIMc];   // row-major, same permutation
__device__ float g_O[Bb*Nn*DIMc];   // row-major
__device__ float g_X[Bb*Nn*DIMc];   // row-major, tf32-rounded
__device__ float g_Wq[DIMc*DIMc];   // B-FRAGMENT layout, tf32-rounded
__device__ float g_Wk[DIMc*DIMc];
__device__ float g_Wv[DIMc*DIMc];
__device__ float g_Wo[DIMc*DIMc];
__device__ int   g_perm[Bb*Nn];
__device__ int   g_cnt[Bb];
__device__ float g_C[Bb*DIMc];

// B-fragment layout (weights): word index ((nb*16+kc)*4+s)*64 + lane*2 + e
//   nb = n>>3, kc = k>>5, s = (k>>3)&3, lane = (n&7)*4 + (k&3), e = (k>>2)&1

__device__ __forceinline__ unsigned f2tf(float x) {
    unsigned u;
    asm("cvt.rna.tf32.f32 %0, %1;" : "=r"(u) : "f"(x));
    return u;
}

__device__ __forceinline__ void mma_tf32(
    float c[4], unsigned a0, unsigned a1, unsigned a2, unsigned a3,
    unsigned b0, unsigned b1)
{
    asm volatile(
        "mma.sync.aligned.m16n8k8.row.col.f32.tf32.tf32.f32 "
        "{%0,%1,%2,%3},{%4,%5,%6,%7},{%8,%9},{%0,%1,%2,%3};\n"
        : "+f"(c[0]), "+f"(c[1]), "+f"(c[2]), "+f"(c[3])
        : "r"(a0), "r"(a1), "r"(a2), "r"(a3), "r"(b0), "r"(b1));
}

__device__ __forceinline__ void cpa16(unsigned saddr, const void* g) {
    asm volatile("cp.async.ca.shared.global [%0], [%1], 16;" :: "r"(saddr), "l"(g));
}
__device__ __forceinline__ void cpa4(unsigned saddr, const void* g) {
    asm volatile("cp.async.ca.shared.global [%0], [%1], 4;" :: "r"(saddr), "l"(g));
}
__device__ __forceinline__ uint32_t smem_u32(const void* p) {
    return (uint32_t)__cvta_generic_to_shared(p);
}

// ---------------------------------------------------------------------------
// Fused pre-pass: X -> linear tf32 round; weights -> tf32 round + B-fragment
// permute. One launch.
// ---------------------------------------------------------------------------
#define NX (Bb*Nn*DIMc)
#define NW (DIMc*DIMc)
#define NXW (NX/4)          // float4 groups for X
#define NWG (NW/2)          // B-layout groups of 2 words (= 2^17)
#define NGT (NXW + 4*NWG)

__global__ __launch_bounds__(256) void round_all_kernel(
    const float* __restrict__ X,  const float* __restrict__ Wq,
    const float* __restrict__ Wk, const float* __restrict__ Wv,
    const float* __restrict__ Wo)
{
    const int gid = blockIdx.x * 256 + threadIdx.x;
    if (gid >= NGT) return;
    if (gid < NXW) {
        const int i = gid * 4;
        float4 v = *(const float4*)(X + i);
        uint4 u;
        u.x = f2tf(v.x); u.y = f2tf(v.y); u.z = f2tf(v.z); u.w = f2tf(v.w);
        *(uint4*)&g_X[i] = u;
    } else {
        const int wi = (gid - NXW) >> 17;          // NWG = 2^17
        const int g  = (gid - NXW) & (NWG - 1);
        const float* W = (wi == 0) ? Wq : (wi == 1) ? Wk : (wi == 2) ? Wv : Wo;
        float* D = (wi == 0) ? g_Wq : (wi == 1) ? g_Wk : (wi == 2) ? g_Wv : g_Wo;
        const int lane = g & 31;
        const int s    = (g >> 5) & 3;
        const int kc   = (g >> 7) & 15;
        const int nb   = g >> 11;
        const int q    = lane >> 2, r = lane & 3;
        const int n    = nb * 8 + q;
        const int k    = kc * 32 + s * 8 + r;
        uint2 u;
        u.x = f2tf(W[(size_t)n * DIMc + k]);       // e=0 -> b0 (k = r)
        u.y = f2tf(W[(size_t)n * DIMc + k + 4]);   // e=1 -> b1 (k = r+4)
        *(uint2*)&D[(size_t)g * 2] = u;
    }
}

// ---------------------------------------------------------------------------
// Scan: per batch, stable partition of key indices (unmasked first).
// Also zeros g_C for this batch (saves a launch).
// ---------------------------------------------------------------------------
__global__ __launch_bounds__(256) void scan_kernel(const int* __restrict__ mask)
{
    __shared__ int ssum[256];
    __shared__ int cnt_s;
    const int b = blockIdx.x, t = threadIdx.x;
    g_C[b * DIMc + t]       = 0.f;
    g_C[b * DIMc + t + 256] = 0.f;
    const int base = b * Nn + t * 8;
    int m[8], s = 0;
    #pragma unroll
    for (int i = 0; i < 8; i++) { m[i] = (mask[base + i] != 0); s += m[i]; }
    ssum[t] = s;
    __syncthreads();
    int ex = 0;
    for (int j = 0; j < t; j++) ex += ssum[j];
    if (t == 255) cnt_s = ex + ssum[255];
    __syncthreads();
    const int cnt = cnt_s;
    int u = ex;
    #pragma unroll
    for (int i = 0; i < 8; i++) {
        int n = t * 8 + i;
        g_perm[base + i] = m[i] ? u : cnt + (n - u);
        u += m[i];
    }
    if (t == 0) g_cnt[b] = cnt;
}

// ---------------------------------------------------------------------------
// C_b = sum of masked (tail) V rows. grid (Bb, 16) x 128 threads, atomics.
// ---------------------------------------------------------------------------
__global__ __launch_bounds__(128) void cb_kernel()
{
    const int b = blockIdx.x;
    const int j = blockIdx.y;
    const int t = threadIdx.x;
    const int cnt   = g_cnt[b];
    const int nmask = Nn - cnt;
    const int chunk = (nmask + 15) >> 4;
    const int start = cnt + j * chunk;
    int end = start + chunk;
    if (end > Nn) end = Nn;
    if (start >= end) return;

    float4 s = make_float4(0.f, 0.f, 0.f, 0.f);
    const float* vb = g_V + (size_t)b * Nn * DIMc + t * 4;
    for (int i = start; i < end; i++) {
        float4 v = *(const float4*)(vb + (size_t)i * DIMc);
        s.x += v.x; s.y += v.y; s.z += v.z; s.w += v.w;
    }
    float* c = g_C + b * DIMc + t * 4;
    atomicAdd(c + 0, s.x);
    atomicAdd(c + 1, s.y);
    atomicAdd(c + 2, s.z);
    atomicAdd(c + 3, s.w);
}

// ---------------------------------------------------------------------------
// tf32 GEMM v3b: A row-major (stride-36 smem staging, as R11); B in fragment
// layout (linear 16KB staging, LDS.64 fragment reads). Block 128x128,
// 4 warps, warp 64x64, BK=32, cp.async double-buffered.
// Per chunk: 64 A-LDS + 32 B-LDS + 128 mma (was 128 LDS).
// ---------------------------------------------------------------------------
#define GSTRIDE 36
#define GABUF (128*GSTRIDE)      // 4608 words per A buffer
#define GBBUF 4096               // words per B buffer (16 nb x 4 s x 64)
#define GEMM_SMEM_BYTES ((2*GABUF + 2*GBBUF) * 4)

template<bool ROUND, bool PERM>
__device__ __forceinline__ void gemm_v3b(
    const float* __restrict__ A, const float* __restrict__ W, float* __restrict__ C)
{
    extern __shared__ __align__(16) unsigned gsm[];
    const unsigned sA = smem_u32(gsm);
    const unsigned sB = sA + 2*GABUF*4;

    const int t    = threadIdx.x;
    const int lane = t & 31;
    const int w    = t >> 5;
    const int q    = lane >> 2;
    const int r    = lane & 3;
    const int wm   = (w >> 1) * 64;
    const int wn   = (w & 1) * 64;
    const int m0   = blockIdx.y * 128;
    const int n0   = blockIdx.x * 128;

    auto stage = [&](int kc, int bf) {
        const float* gA = A + (size_t)m0 * DIMc + kc * 32;
        #pragma unroll
        for (int i = 0; i < 8; i++) {
            const int id = t + 128 * i;                 // 0..1023 16B chunks
            // A: row-major, padded stride 36
            const int row = id >> 3, c16 = id & 7;
            cpa16(sA + (bf*GABUF + row*GSTRIDE + c16*4)*4,
                  gA + (size_t)row * DIMc + c16 * 4);
            // B: fragment blocks (nb, kc) of 256 consecutive words
            const float* gB = W + ((size_t)((n0 >> 3) + (id >> 6)) * 16 + kc) * 256
                                + (id & 63) * 4;
            cpa16(sB + bf*GBBUF*4 + id*16, gB);
        }
        asm volatile("cp.async.commit_group;");
    };

    float acc[4][8][4] = {};
    stage(0, 0);

    #pragma unroll 1
    for (int kt = 0; kt < 16; kt++) {
        const int bf = kt & 1;
        if (kt + 1 < 16) {
            stage(kt + 1, bf ^ 1);
            asm volatile("cp.async.wait_group 1;");
        } else {
            asm volatile("cp.async.wait_group 0;");
        }
        __syncthreads();

        const unsigned* Ab  = gsm + bf*GABUF;
        const unsigned* Bbf = gsm + 2*GABUF + bf*GBBUF;

        #pragma unroll
        for (int s = 0; s < 4; s++) {
            unsigned a[4][4];
            uint2 b2[8];
            #pragma unroll
            for (int i = 0; i < 4; i++) {
                const int r0 = (wm + 16*i + q) * GSTRIDE + 8*s + r;
                a[i][0] = Ab[r0];
                a[i][1] = Ab[r0 + 8*GSTRIDE];
                a[i][2] = Ab[r0 + 4];
                a[i][3] = Ab[r0 + 8*GSTRIDE + 4];
            }
            #pragma unroll
            for (int j = 0; j < 8; j++)
                b2[j] = *(const uint2*)&Bbf[((wn >> 3) + j) * 256 + s*64 + lane*2];
            #pragma unroll
            for (int i = 0; i < 4; i++)
                #pragma unroll
                for (int j = 0; j < 8; j++)
                    mma_tf32(acc[i][j], a[i][0], a[i][1], a[i][2], a[i][3],
                             b2[j].x, b2[j].y);
        }
        __syncthreads();
    }

    #pragma unroll
    for (int i = 0; i < 4; i++) {
        int row0 = m0 + wm + 16*i + q;
        int row1 = row0 + 8;
        if (PERM) {
            row0 = (row0 & ~(Nn-1)) + g_perm[row0];
            row1 = (row1 & ~(Nn-1)) + g_perm[row1];
        }
        #pragma unroll
        for (int j = 0; j < 8; j++) {
            const int col = n0 + wn + 8*j + 2*r;
            float2 v0, v1;
            if (ROUND) {
                v0.x = __uint_as_float(f2tf(acc[i][j][0]));
                v0.y = __uint_as_float(f2tf(acc[i][j][1]));
                v1.x = __uint_as_float(f2tf(acc[i][j][2]));
                v1.y = __uint_as_float(f2tf(acc[i][j][3]));
            } else {
                v0.x = acc[i][j][0]; v0.y = acc[i][j][1];
                v1.x = acc[i][j][2]; v1.y = acc[i][j][3];
            }
            *(float2*)&C[(size_t)row0 * DIMc + col] = v0;
            *(float2*)&C[(size_t)row1 * DIMc + col] = v1;
        }
    }
}

__global__ __launch_bounds__(128) void qkv_kernel()
{
    if (blockIdx.z == 0)      gemm_v3b<true,  false>(g_X, g_Wq, g_Q);
    else if (blockIdx.z == 1) gemm_v3b<true,  true >(g_X, g_Wk, g_K);
    else                      gemm_v3b<true,  true >(g_X, g_Wv, g_V);
}

__global__ __launch_bounds__(128) void proj_kernel(float* __restrict__ out)
{
    gemm_v3b<false, false>(g_O, g_Wo, out);
}

// ---------------------------------------------------------------------------
// Attention v7 (EXACTLY R11; compacted keys). q-tile 128, 128 threads,
// 4 warps x 32 q-rows. K stride 68 / V stride 72, cp.async double-buffer.
// ---------------------------------------------------------------------------
#define AKW (64*68)
#define AVW (64*72)
#define ATTN_SMEM_BYTES ((2*AKW + 2*AVW) * 4)

__global__ __launch_bounds__(128) void attn_kernel()
{
    extern __shared__ __align__(16) unsigned dynsmem[];
    unsigned* KS = dynsmem;
    unsigned* VS = dynsmem + 2*AKW;
    const unsigned sK = smem_u32(KS);
    const unsigned sV = smem_u32(VS);

    const int b    = blockIdx.z;
    const int h    = blockIdx.y;
    const int qt   = blockIdx.x;
    const int t    = threadIdx.x;
    const int lane = t & 31;
    const int w    = t >> 5;
    const int q    = lane >> 2;
    const int r    = lane & 3;

    const int n_act  = g_cnt[b];
    const int n_iter = (n_act + 63) >> 6;

    unsigned q_a[2][8][4];
    {
        const float* qb = g_Q + ((size_t)(b*Nn + qt*128 + w*32)) * DIMc + h*DHh;
        #pragma unroll
        for (int m = 0; m < 2; m++) {
            #pragma unroll
            for (int s = 0; s < 8; s++) {
                const float* p0 = qb + (16*m + q) * DIMc + 8*s + r;
                q_a[m][s][0] = __float_as_uint(p0[0]);
                q_a[m][s][1] = __float_as_uint(p0[8*DIMc]);
                q_a[m][s][2] = __float_as_uint(p0[4]);
                q_a[m][s][3] = __float_as_uint(p0[8*DIMc + 4]);
            }
        }
    }

    auto stage = [&](int kt, int bf) {
        #pragma unroll
        for (int i = 0; i < 8; i++) {
            int id  = t + 128 * i;
            int row = id >> 4, c4 = id & 15;
            const float* gk = &g_K[((size_t)b*Nn + kt*64 + row)*DIMc + h*DHh + c4*4];
            const float* gv = &g_V[((size_t)b*Nn + kt*64 + row)*DIMc + h*DHh + c4*4];
            cpa16(sK + (bf*AKW + row*68 + c4*4)*4, gk);
            cpa16(sV + (bf*AVW + row*72 + c4*4)*4, gv);
        }
        asm volatile("cp.async.commit_group;");
    };

    if (n_iter > 0) stage(0, 0);

    float o_acc[2][8][4] = {};
    float lsum[2][2] = {};
    const int srcA = 4*q + (r >> 1);
    const int srcB = srcA + 2;
    const bool hi  = (r & 1);

    #pragma unroll 1
    for (int kt = 0; kt < n_iter; kt++) {
        const int bf = kt & 1;
        if (kt + 1 < n_iter) {
            stage(kt + 1, bf ^ 1);
            asm volatile("cp.async.wait_group 1;");
        } else {
            asm volatile("cp.async.wait_group 0;");
        }
        __syncthreads();

        const unsigned* Kb = KS + bf*AKW;
        const unsigned* Vb = VS + bf*AVW;

        #pragma unroll
        for (int half = 0; half < 2; half++) {
            float sc[2][4][4] = {};
            #pragma unroll
            for (int s = 0; s < 8; s++) {
                #pragma unroll
                for (int j = 0; j < 4; j++) {
                    const int bi = ((half*4 + j)*8 + q) * 68 + 8*s + r;
                    const unsigned b0 = Kb[bi], b1 = Kb[bi + 4];
                    mma_tf32(sc[0][j], q_a[0][s][0], q_a[0][s][1],
                             q_a[0][s][2], q_a[0][s][3], b0, b1);
                    mma_tf32(sc[1][j], q_a[1][s][0], q_a[1][s][1],
                             q_a[1][s][2], q_a[1][s][3], b0, b1);
                }
            }

            #pragma unroll
            for (int m = 0; m < 2; m++) {
                #pragma unroll
                for (int j = 0; j < 4; j++) {
                    const int k0 = kt*64 + (half*4 + j)*8 + 2*r;
                    const bool in0 = (k0     < n_act);
                    const bool in1 = (k0 + 1 < n_act);
                    float p00 = in0 ? __expf(sc[m][j][0] * SCALE) : 0.0f;
                    float p01 = in1 ? __expf(sc[m][j][1] * SCALE) : 0.0f;
                    float p10 = in0 ? __expf(sc[m][j][2] * SCALE) : 0.0f;
                    float p11 = in1 ? __expf(sc[m][j][3] * SCALE) : 0.0f;
                    lsum[m][0] += p00 + p01;
                    lsum[m][1] += p10 + p11;
                    sc[m][j][0] = p00; sc[m][j][1] = p01;
                    sc[m][j][2] = p10; sc[m][j][3] = p11;
                }
            }

            #pragma unroll
            for (int s2 = 0; s2 < 4; s2++) {
                unsigned pa[2][4];
                #pragma unroll
                for (int m = 0; m < 2; m++) {
                    float x0 = __shfl_sync(0xffffffffu, sc[m][s2][0], srcA);
                    float x1 = __shfl_sync(0xffffffffu, sc[m][s2][1], srcA);
                    float x2 = __shfl_sync(0xffffffffu, sc[m][s2][2], srcA);
                    float x3 = __shfl_sync(0xffffffffu, sc[m][s2][3], srcA);
                    float y0 = __shfl_sync(0xffffffffu, sc[m][s2][0], srcB);
                    float y1 = __shfl_sync(0xffffffffu, sc[m][s2][1], srcB);
                    float y2 = __shfl_sync(0xffffffffu, sc[m][s2][2], srcB);
                    float y3 = __shfl_sync(0xffffffffu, sc[m][s2][3], srcB);
                    pa[m][0] = f2tf(hi ? x1 : x0);
                    pa[m][1] = f2tf(hi ? x3 : x2);
                    pa[m][2] = f2tf(hi ? y1 : y0);
                    pa[m][3] = f2tf(hi ? y3 : y2);
                }
                const int krow = (half*32 + 8*s2 + r) * 72;
                #pragma unroll
                for (int j2 = 0; j2 < 8; j2++) {
                    const unsigned v0 = Vb[krow + 8*j2 + q];
                    const unsigned v1 = Vb[krow + 8*j2 + q + 4*72];
                    mma_tf32(o_acc[0][j2], pa[0][0], pa[0][1], pa[0][2], pa[0][3], v0, v1);
                    mma_tf32(o_acc[1][j2], pa[1][0], pa[1][1], pa[1][2], pa[1][3], v0, v1);
                }
            }
        }
        __syncthreads();
    }

    const float mcount = (float)(Nn - n_act);
    #pragma unroll
    for (int m = 0; m < 2; m++) {
        float l0 = lsum[m][0], l1 = lsum[m][1];
        l0 += __shfl_xor_sync(0xffffffffu, l0, 1);
        l0 += __shfl_xor_sync(0xffffffffu, l0, 2);
        l1 += __shfl_xor_sync(0xffffffffu, l1, 1);
        l1 += __shfl_xor_sync(0xffffffffu, l1, 2);
        const float inv0 = 1.f / (l0 + mcount);
        const float inv1 = 1.f / (l1 + mcount);
        const int grow = b*Nn + qt*128 + w*32 + 16*m + q;
        #pragma unroll
        for (int j2 = 0; j2 < 8; j2++) {
            const int col = h*DHh + 8*j2 + 2*r;
            const float2 cv = *(const float2*)&g_C[b*DIMc + col];
            float2 v0, v1;
            v0.x = __uint_as_float(f2tf((o_acc[m][j2][0] + cv.x) * inv0));
            v0.y = __uint_as_float(f2tf((o_acc[m][j2][1] + cv.y) * inv0));
            v1.x = __uint_as_float(f2tf((o_acc[m][j2][2] + cv.x) * inv1));
            v1.y = __uint_as_float(f2tf((o_acc[m][j2][3] + cv.y) * inv1));
            *(float2*)&g_O[(size_t)grow * DIMc + col]       = v0;
            *(float2*)&g_O[(size_t)(grow + 8) * DIMc + col] = v1;
        }
    }
}

extern "C" void kernel_launch(void* const* d_in, const int* in_sizes, int n_in,
                              void* d_out, int out_size)
{
    const float* X    = (const float*)d_in[0];
    const int*   mask = (const int*)  d_in[1];
    const float* Wq   = (const float*)d_in[2];
    const float* Wk   = (const float*)d_in[3];
    const float* Wv   = (const float*)d_in[4];
    const float* Wout = (const float*)d_in[5];
    float* out = (float*)d_out;

    cudaFuncSetAttribute(attn_kernel,
                         cudaFuncAttributeMaxDynamicSharedMemorySize, ATTN_SMEM_BYTES);
    cudaFuncSetAttribute(qkv_kernel,
                         cudaFuncAttributeMaxDynamicSharedMemorySize, GEMM_SMEM_BYTES);
    cudaFuncSetAttribute(proj_kernel,
                         cudaFuncAttributeMaxDynamicSharedMemorySize, GEMM_SMEM_BYTES);

    round_all_kernel<<<(NGT + 255)/256, 256>>>(X, Wq, Wk, Wv, Wout);
    scan_kernel<<<Bb, 256>>>(mask);

    dim3 g_qkv(DIMc/128, (Bb*Nn)/128, 3);
    qkv_kernel<<<g_qkv, 128, GEMM_SMEM_BYTES>>>();

    cb_kernel<<<dim3(Bb, 16), 128>>>();

    dim3 g_attn(Nn/128, Hh, Bb);
    attn_kernel<<<g_attn, 128, ATTN_SMEM_BYTES>>>();

    dim3 g_proj(DIMc/128, (Bb*Nn)/128, 1);
    proj_kernel<<<g_proj, 128, GEMM_SMEM_BYTES>>>(out);
}